// round 9
// baseline (speedup 1.0000x reference)
#include <cuda_runtime.h>
#include <cuda_bf16.h>
#include <cstdint>

#define N_NODES 100000
#define N_EDGES 3200000
#define IN_CH   128
#define HID     32
#define OUT_CH  64
#define N_SG    31
#define N_RAW   (N_EDGES + N_NODES)          // edges + self loops (unpadded)
#define N_PAD_MAX (N_EDGES + 4 * N_NODES)    // padded CSR capacity (3.6M, mult of 4)

// ---------------- device scratch (static globals; no allocation) ----------------
__device__ int    g_is64;
__device__ int    g_deg[N_NODES];
__device__ float  g_dinv[N_NODES];
__device__ int    g_offs[N_NODES + 1];
__device__ int    g_cursor[N_NODES];
__device__ int4   g_csr4[N_PAD_MAX / 4];             // src indices, padded w/ sentinel N_NODES
__device__ float4 g_h[2][(size_t)(N_NODES + 1) * 8]; // ping-pong scaled state h' (row N_NODES = zeros)

// Safe edge accessor: idx in [0, 2*N_EDGES)
__device__ __forceinline__ int edge_at(const void* ei, size_t idx) {
    int v = g_is64 ? (int)((const long long*)ei)[idx]
                   : ((const int*)ei)[idx];
    return min(max(v, 0), N_NODES - 1);
}

// ---------------- launch 1: dtype detect + deg init ----------------
__global__ void k_detect_init(const int* __restrict__ w) {
    int i = blockIdx.x * blockDim.x + threadIdx.x;
    if (i < N_NODES) g_deg[i] = 1;  // self loop
    if (blockIdx.x == 0) {
        __shared__ int any_nonzero;
        if (threadIdx.x == 0) any_nonzero = 0;
        __syncthreads();
        size_t pos = (size_t)threadIdx.x * 24994 + 1;   // tid<256 -> max 6.37M
        if (w[pos] != 0) any_nonzero = 1;
        __syncthreads();
        if (threadIdx.x == 0) g_is64 = any_nonzero ? 0 : 1;
    }
}

// ---------------- launch 2: degree accumulation ----------------
__global__ void k_deg_accum(const void* __restrict__ ei) {
    int i = blockIdx.x * blockDim.x + threadIdx.x;
    if (i < N_EDGES) {
        int c = edge_at(ei, (size_t)N_EDGES + i);   // col = edge_index[1] (dst)
        atomicAdd(&g_deg[c], 1);
    }
}

// ---------------- launch 3: dinv + padded exclusive scan (single block) ----------------
__global__ void k_scan_dinv() {
    __shared__ int part[1024];
    const int tid = threadIdx.x;
    const int chunk = (N_NODES + 1023) / 1024;
    int beg = tid * chunk;
    int end = min(beg + chunk, N_NODES);
    int s = 0;
    for (int i = beg; i < end; i++) {
        int d = g_deg[i];
        g_dinv[i] = rsqrtf((float)d);
        s += (d + 3) & ~3;                      // padded degree
    }
    part[tid] = s;
    __syncthreads();
    for (int off = 1; off < 1024; off <<= 1) {
        int v = (tid >= off) ? part[tid - off] : 0;
        __syncthreads();
        part[tid] += v;
        __syncthreads();
    }
    int run = (tid == 0) ? 0 : part[tid - 1];
    for (int i = beg; i < end; i++) { g_offs[i] = run; run += (g_deg[i] + 3) & ~3; }
    if (tid == 1023) g_offs[N_NODES] = run;
}

// ---------------- launch 4: cursor init + CSR sentinel fill + zero sentinel h rows ----------------
__global__ void k_prep() {
    int i = blockIdx.x * blockDim.x + threadIdx.x;
    if (i < N_NODES) g_cursor[i] = g_offs[i];
    if (i < N_PAD_MAX / 4) g_csr4[i] = make_int4(N_NODES, N_NODES, N_NODES, N_NODES);
    if (i < 64) {  // zero row N_NODES of both ping-pong buffers
        ((float*)g_h[i >> 5])[(size_t)N_NODES * 32 + (i & 31)] = 0.f;
    }
}

// ---------------- launch 5: CSR fill (+ self loops)  AND  conv0 (fused) ----------------
#define FILL_B ((N_RAW + 255) / 256)         // 12891
#define CONV_B ((N_NODES + 7) / 8)           // 12500
__global__ void __launch_bounds__(256) k_fill_conv0(const void* __restrict__ ei,
                                                    const float* __restrict__ x,
                                                    const float* __restrict__ W0,
                                                    const float* __restrict__ b0) {
    __shared__ float Wsm[IN_CH * HID];   // 16 KB (used by conv0 blocks only)
    __shared__ float bsm[HID];
    if (blockIdx.x < FILL_B) {
        int i = blockIdx.x * blockDim.x + threadIdx.x;
        int* csr = (int*)g_csr4;
        if (i < N_EDGES) {
            int r = edge_at(ei, (size_t)i);               // src
            int c = edge_at(ei, (size_t)N_EDGES + i);     // dst
            int pos = atomicAdd(&g_cursor[c], 1);
            csr[min(max(pos, 0), N_PAD_MAX - 1)] = r;
        } else if (i < N_RAW) {
            int n = i - N_EDGES;
            int pos = atomicAdd(&g_cursor[n], 1);
            csr[min(max(pos, 0), N_PAD_MAX - 1)] = n;     // self loop
        }
        return;
    }
    // ---- conv0: h'0 = dinv * (x @ W0 + b0) ----
    for (int i = threadIdx.x; i < IN_CH * HID; i += blockDim.x) Wsm[i] = W0[i];
    if (threadIdx.x < HID) bsm[threadIdx.x] = b0[threadIdx.x];
    __syncthreads();
    int node = (blockIdx.x - FILL_B) * 8 + (threadIdx.x >> 5);
    int lane = threadIdx.x & 31;
    if (node >= N_NODES) return;
    float xr[4];
#pragma unroll
    for (int q = 0; q < 4; q++) xr[q] = x[(size_t)node * IN_CH + q * 32 + lane];
    float y = bsm[lane];
#pragma unroll
    for (int q = 0; q < 4; q++)
#pragma unroll
        for (int c = 0; c < 32; c++) {
            float xv = __shfl_sync(0xffffffffu, xr[q], c);
            y = fmaf(xv, Wsm[(q * 32 + c) * HID + lane], y);
        }
    ((float*)g_h[0])[(size_t)node * 32 + lane] = y * g_dinv[node];
}

// ---------------- launches 6..36: SG layer ----------------
// agg = dinv[dst] * sum_{src in N(dst)} h'[src];  h'_out = dinv[dst]*relu(agg@W + b)
__device__ __forceinline__ int pick_lane(int4 s, int grp) {
    return (grp == 0) ? s.x : (grp == 1) ? s.y : (grp == 2) ? s.z : s.w;
}

__global__ void __launch_bounds__(256) k_sg_layer(int parity, const float* __restrict__ W,
                                                  const float* __restrict__ b) {
    __shared__ float Wsm[HID * HID];
    __shared__ float bsm[HID];
    for (int i = threadIdx.x; i < HID * HID; i += blockDim.x) Wsm[i] = W[i];
    if (threadIdx.x < HID) bsm[threadIdx.x] = b[threadIdx.x];
    __syncthreads();
    int node = blockIdx.x * 8 + (threadIdx.x >> 5);
    int lane = threadIdx.x & 31;
    if (node >= N_NODES) return;

    const float4* __restrict__ hin = g_h[parity];
    float* __restrict__ hout = (float*)g_h[parity ^ 1];

    int e4   = g_offs[node] >> 2;
    int end4 = g_offs[node + 1] >> 2;
    const int grp = lane >> 3, sub = lane & 7;

    float4 a0 = make_float4(0.f, 0.f, 0.f, 0.f);
    float4 a1 = make_float4(0.f, 0.f, 0.f, 0.f);
    float4 a2 = make_float4(0.f, 0.f, 0.f, 0.f);
    float4 a3 = make_float4(0.f, 0.f, 0.f, 0.f);

    // 16 edges per iteration: 4 CSR quads, 4 independent gathers in flight
    for (; e4 + 4 <= end4; e4 += 4) {
        int4 s0 = __ldg(&g_csr4[e4]);
        int4 s1 = __ldg(&g_csr4[e4 + 1]);
        int4 s2 = __ldg(&g_csr4[e4 + 2]);
        int4 s3 = __ldg(&g_csr4[e4 + 3]);
        int i0 = pick_lane(s0, grp) * 8 + sub;
        int i1 = pick_lane(s1, grp) * 8 + sub;
        int i2 = pick_lane(s2, grp) * 8 + sub;
        int i3 = pick_lane(s3, grp) * 8 + sub;
        float4 v0 = hin[i0];
        float4 v1 = hin[i1];
        float4 v2 = hin[i2];
        float4 v3 = hin[i3];
        a0.x += v0.x; a0.y += v0.y; a0.z += v0.z; a0.w += v0.w;
        a1.x += v1.x; a1.y += v1.y; a1.z += v1.z; a1.w += v1.w;
        a2.x += v2.x; a2.y += v2.y; a2.z += v2.z; a2.w += v2.w;
        a3.x += v3.x; a3.y += v3.y; a3.z += v3.z; a3.w += v3.w;
    }
    for (; e4 < end4; e4++) {
        int4 s0 = __ldg(&g_csr4[e4]);
        int i0 = pick_lane(s0, grp) * 8 + sub;
        float4 v0 = hin[i0];
        a0.x += v0.x; a0.y += v0.y; a0.z += v0.z; a0.w += v0.w;
    }
    a0.x += a1.x; a0.y += a1.y; a0.z += a1.z; a0.w += a1.w;
    a2.x += a3.x; a2.y += a3.y; a2.z += a3.z; a2.w += a3.w;
    a0.x += a2.x; a0.y += a2.y; a0.z += a2.z; a0.w += a2.w;

    // reduce across the 4 lane groups: channel c ends up (replicated) at
    // lane (c>>2) [within group 0..7], component (c&3)
#pragma unroll
    for (int d = 8; d <= 16; d <<= 1) {
        a0.x += __shfl_xor_sync(0xffffffffu, a0.x, d);
        a0.y += __shfl_xor_sync(0xffffffffu, a0.y, d);
        a0.z += __shfl_xor_sync(0xffffffffu, a0.z, d);
        a0.w += __shfl_xor_sync(0xffffffffu, a0.w, d);
    }

    // GEMM directly from distributed layout: y_raw = sum_c agg[c] * W[c][lane]
    float y = 0.f;
#pragma unroll
    for (int c = 0; c < 32; c++) {
        float comp = (c & 3) == 0 ? a0.x : (c & 3) == 1 ? a0.y : (c & 3) == 2 ? a0.z : a0.w;
        float v = __shfl_sync(0xffffffffu, comp, c >> 2);
        y = fmaf(v, Wsm[c * HID + lane], y);
    }
    float dv = g_dinv[node];
    float t = fmaf(y, dv, bsm[lane]);               // agg scaled by dinv, + bias
    hout[node * 32 + lane] = fmaxf(t, 0.f) * dv;    // pre-scale for next layer
}

// ---------------- final launch: out = h @ W32 + b32  (unscale h' by sqrt(deg)) ----------------
__global__ void k_conv_out(int parity, const float* __restrict__ W32,
                           const float* __restrict__ b32, float* __restrict__ out) {
    __shared__ float Wsm[HID * OUT_CH];  // 8 KB
    __shared__ float bsm[OUT_CH];
    for (int i = threadIdx.x; i < HID * OUT_CH; i += blockDim.x) Wsm[i] = W32[i];
    if (threadIdx.x < OUT_CH) bsm[threadIdx.x] = b32[threadIdx.x];
    __syncthreads();
    int node = blockIdx.x * 8 + (threadIdx.x >> 5);
    int lane = threadIdx.x & 31;
    if (node >= N_NODES) return;
    float hv = ((const float*)g_h[parity])[(size_t)node * 32 + lane]
               * sqrtf((float)g_deg[node]);   // undo the dinv pre-scale
    float y0 = bsm[lane], y1 = bsm[lane + 32];
#pragma unroll
    for (int c = 0; c < 32; c++) {
        float a = __shfl_sync(0xffffffffu, hv, c);
        y0 = fmaf(a, Wsm[c * OUT_CH + lane], y0);
        y1 = fmaf(a, Wsm[c * OUT_CH + lane + 32], y1);
    }
    out[(size_t)node * OUT_CH + lane]      = y0;
    out[(size_t)node * OUT_CH + lane + 32] = y1;
}

// ---------------- launch ----------------
extern "C" void kernel_launch(void* const* d_in, const int* in_sizes, int n_in,
                              void* d_out, int out_size) {
    const float* x = nullptr; const float* W0 = nullptr; const float* b0 = nullptr;
    const float* Ws = nullptr; const float* bs = nullptr;
    const float* W32 = nullptr; const float* b32 = nullptr;
    const void* ei = nullptr;
    for (int i = 0; i < n_in; i++) {
        switch (in_sizes[i]) {
            case 12800000: x   = (const float*)d_in[i]; break;
            case 4096:     W0  = (const float*)d_in[i]; break;
            case 32:       b0  = (const float*)d_in[i]; break;
            case 31744:    Ws  = (const float*)d_in[i]; break;
            case 992:      bs  = (const float*)d_in[i]; break;
            case 2048:     W32 = (const float*)d_in[i]; break;
            case 64:       b32 = (const float*)d_in[i]; break;
            case 6400000:  ei  = d_in[i]; break;
            default: break;
        }
    }
    if (!x || !W0 || !b0 || !Ws || !bs || !W32 || !b32 || !ei) return;

    float* out = (float*)d_out;
    const int T = 256;

    k_detect_init<<<(N_NODES + T - 1) / T, T>>>((const int*)ei);          // 1
    k_deg_accum<<<(N_EDGES + T - 1) / T, T>>>(ei);                        // 2
    k_scan_dinv<<<1, 1024>>>();                                           // 3
    k_prep<<<(N_PAD_MAX / 4 + T - 1) / T, T>>>();                         // 4
    k_fill_conv0<<<FILL_B + CONV_B, T>>>(ei, x, W0, b0);                  // 5

    int parity = 0;
    for (int l = 0; l < N_SG; l++) {                                      // 6..36
        k_sg_layer<<<CONV_B, T>>>(parity, Ws + (size_t)l * HID * HID, bs + (size_t)l * HID);
        parity ^= 1;
    }

    k_conv_out<<<CONV_B, T>>>(parity, W32, b32, out);                     // 37
}